// round 16
// baseline (speedup 1.0000x reference)
#include <cuda_runtime.h>

// LUT-tree conv: B=8, C=64, H=W=32, O=32, Q=8, K=3.
// R15: coefficient path moved to __constant__ memory.
//      prep_kernel (32 blocks) does Möbius transform + 0.5-folding + sigmoid
//      -log2e pre-scaling once for all (o,lut); 53KB copied to const via
//      graph-capturable D2D cudaMemcpyToSymbolAsync. Main kernel (R9 winner
//      structure: 128thr/2px, quarter-H, rolling rows) loses all coeff LDS,
//      the per-block staging prologue, and ~16 coeff registers; eval sigmoids
//      lose their FMUL (scale folded into tables).

#define STRIDE 36
#define HROWS  10                    // 8 output rows + 2 halo
#define PLANE  (HROWS * STRIDE)      // 360 floats per channel plane
#define NTBL   (32 * 26 * 16)        // 13312 floats = 53248 B

__device__   float g_wc[NTBL];       // prepass output
__constant__ float cWc[NTBL];        // const copy read by main kernel

// sigmoid for FILL (raw x): 2 MUFU + FMUL + FADD
__device__ __forceinline__ float fsig(float x) {
    float e, r;
    asm("ex2.approx.f32 %0, %1;" : "=f"(e) : "f"(x * -1.4426950408889634f));
    asm("rcp.approx.f32 %0, %1;" : "=f"(r) : "f"(1.0f + e));
    return r;
}
// sigmoid for EVAL: table already scaled by -log2e, so y = -x*log2(e) arrives
__device__ __forceinline__ float fsig_s(float y) {
    float e, r;
    asm("ex2.approx.f32 %0, %1;" : "=f"(e) : "f"(y));
    asm("rcp.approx.f32 %0, %1;" : "=f"(r) : "f"(1.0f + e));
    return r;
}

// Horner eval of multilinear interp with Möbius coeffs: 15 FMA, zero FADD.
__device__ __forceinline__ float lut4m(const float c[16],
                                       float x0, float x1, float x2, float x3) {
    float u0 = fmaf(x0, c[1],  c[0]);
    float u1 = fmaf(x0, c[3],  c[2]);
    float u2 = fmaf(x0, c[5],  c[4]);
    float u3 = fmaf(x0, c[7],  c[6]);
    float u4 = fmaf(x0, c[9],  c[8]);
    float u5 = fmaf(x0, c[11], c[10]);
    float u6 = fmaf(x0, c[13], c[12]);
    float u7 = fmaf(x0, c[15], c[14]);
    float v0 = fmaf(x1, u1, u0);
    float v1 = fmaf(x1, u3, u2);
    float v2 = fmaf(x1, u5, u4);
    float v3 = fmaf(x1, u7, u6);
    float w0 = fmaf(x2, v1, v0);
    float w1 = fmaf(x2, v3, v2);
    return fmaf(x3, w1, w0);
}

// 2-input folded LUT: 3 FMA.
__device__ __forceinline__ float lut2m(float4 c, float x0, float x1) {
    return fmaf(x1, fmaf(x0, c.w, c.z), fmaf(x0, c.y, c.x));
}

// Coeff fetch from __constant__ (uniform address -> LDCU/LDC path, off the L1 crossbar).
__device__ __forceinline__ void ldc16(float c[16], const float* base, int lut) {
    const float4* p = reinterpret_cast<const float4*>(base + lut * 16);
    #pragma unroll
    for (int j = 0; j < 4; j++) {
        float4 t = p[j];
        c[4*j+0] = t.x; c[4*j+1] = t.y; c[4*j+2] = t.z; c[4*j+3] = t.w;
    }
}

// ---- Prepass: Möbius transform + constant-fold + sigmoid-scale, all (o,lut) ----
__global__ __launch_bounds__(32) void prep_kernel(
    const float* __restrict__ w0, const float* __restrict__ w1,
    const float* __restrict__ w2, const float* __restrict__ w3)
{
    const int o = blockIdx.x;            // 0..31
    const int t = threadIdx.x;           // lut id
    if (t >= 26) return;
    const float* src;
    if (t < 18)      src = w0 + o * 288 + t * 16;
    else if (t < 23) src = w1 + o * 80  + (t - 18) * 16;
    else if (t < 25) src = w2 + o * 32  + (t - 23) * 16;
    else             src = w3 + o * 16;
    float t16[16];
    #pragma unroll
    for (int i = 0; i < 16; i++) t16[i] = src[i];
    // finite-difference (Möbius) transform along each dim
    #pragma unroll
    for (int d = 0; d < 4; d++) {
        const int s = 1 << d;
        #pragma unroll
        for (int j = 0; j < 16; j++)
            if (j & s) t16[j] -= t16[j ^ s];
    }
    // fold constant-0.5 inputs: LUT22 & LUT25 fold dims 3,2; LUT24 dims 3,2,1.
    const int nfold = (t == 22 || t == 25) ? 2 : (t == 24 ? 3 : 0);
    for (int d = 3; d > 3 - nfold; d--) {
        const int s = 1 << d;
        for (int j = 0; j < s; j++) t16[j] += 0.5f * t16[j + s];
    }
    // pre-scale by -log2(e) for every table whose output feeds a sigmoid (all but 25)
    if (t != 25) {
        #pragma unroll
        for (int i = 0; i < 16; i++) t16[i] *= -1.4426950408889634f;
    }
    #pragma unroll
    for (int i = 0; i < 16; i++) g_wc[(o * 26 + t) * 16 + i] = t16[i];
}

__global__ __launch_bounds__(128, 7) void lut_tree_kernel(
    const float* __restrict__ x, const int* __restrict__ ci,
    float* __restrict__ out)
{
    __shared__ __align__(16) float S[8 * PLANE];   // sigmoided channels + halo

    const int o   = blockIdx.x;          // 0..31
    const int b   = blockIdx.y;          // 0..7
    const int h0  = blockIdx.z << 3;     // 0,8,16,24
    const int tid = threadIdx.x;
    const float* Wb = cWc + o * (26 * 16);   // uniform base for this output unit

    // ---- Init planes to 0.5 (covers conv zero-pad halo) ----
    {
        float4 hv = make_float4(0.5f, 0.5f, 0.5f, 0.5f);
        float4* S4 = reinterpret_cast<float4*>(S);
        for (int i = tid; i < 8 * PLANE / 4; i += 128) S4[i] = hv;
    }
    __syncthreads();

    // ---- Fill interior: sigmoid of selected channels for this h-quarter ----
    #pragma unroll
    for (int q = 0; q < 8; q++) {
        const int ch = ci[o * 8 + q];
        const float* xc = x + ((size_t)(b * 64 + ch)) * 1024;
        #pragma unroll
        for (int i0 = 0; i0 < HROWS * 32; i0 += 128) {
            const int i = i0 + tid;
            if (i < HROWS * 32) {
                const int r = i >> 5, w = i & 31;
                const int hin = h0 - 1 + r;
                if (hin >= 0 && hin < 32)
                    S[q * PLANE + r * STRIDE + 1 + w] = fsig(xc[hin * 32 + w]);
            }
        }
    }
    __syncthreads();

    // ---- Eval: thread -> output row ty (of 8), 2 consecutive cols ----
    const int ty = tid >> 4;              // 0..7
    const int wb = (tid & 15) << 1;       // 0..30 (8B aligned)

    // Rolling feature-row pair: va = row rA, vb = row rA+1 (rA = 4l/3).
    float va[4], vb[4];
    #define LOADROW(dst, R) do {                                               \
        const float* p_ = S + ((R) / 3) * PLANE + (ty + (R) % 3) * STRIDE + wb;\
        float2 f0_ = *(const float2*)p_;                                       \
        float2 f1_ = *(const float2*)(p_ + 2);                                 \
        dst[0] = f0_.x; dst[1] = f0_.y; dst[2] = f1_.x; dst[3] = f1_.y;        \
    } while (0)

    float ing[4][2];   // current level-1 group inputs
    float h1s[2][5];   // sigmoided level-1 outputs per pixel

    LOADROW(va, 0);
    LOADROW(vb, 1);

    #pragma unroll
    for (int l = 0; l < 18; l++) {
        const int k = l & 3;
        const int g = l >> 2;
        const int rA = (4 * l) / 3;
        float c[16]; ldc16(c, Wb, l);
        #pragma unroll
        for (int p = 0; p < 2; p++) {
            float xi[4];
            #pragma unroll
            for (int i = 0; i < 4; i++) {
                const int j  = 4 * l + i;     // compile-time
                const int rr = j / 3;
                const int kw = j % 3;
                xi[i] = (rr == rA) ? va[kw + p] : vb[kw + p];
            }
            ing[k][p] = fsig_s(lut4m(c, xi[0], xi[1], xi[2], xi[3]));
        }
        // level-1 reduction when a group completes
        if (k == 3) {                        // groups 0..3 (full LUT4)
            float cg[16]; ldc16(cg, Wb, 18 + g);
            #pragma unroll
            for (int p = 0; p < 2; p++)
                h1s[p][g] = fsig_s(lut4m(cg, ing[0][p], ing[1][p], ing[2][p], ing[3][p]));
        }
        if (l == 17) {                       // group 4: folded 2-input LUT
            float4 c4 = *reinterpret_cast<const float4*>(Wb + 22 * 16);
            #pragma unroll
            for (int p = 0; p < 2; p++)
                h1s[p][4] = fsig_s(lut2m(c4, ing[0][p], ing[1][p]));
        }
        // advance rolling rows
        if (l < 17) {
            const int rN = (4 * (l + 1)) / 3;
            if (rN == rA + 1) {
                #pragma unroll
                for (int i = 0; i < 4; i++) va[i] = vb[i];
                LOADROW(vb, rN + 1);
            } else {
                LOADROW(va, rN);
                LOADROW(vb, rN + 1);
            }
        }
    }
    #undef LOADROW

    // Level 2: LUT23 full; LUT24 folded to linear (1 FMA).
    float h2s[2][2];
    {
        float c[16]; ldc16(c, Wb, 23);
        #pragma unroll
        for (int p = 0; p < 2; p++)
            h2s[p][0] = fsig_s(lut4m(c, h1s[p][0], h1s[p][1], h1s[p][2], h1s[p][3]));
    }
    {
        float2 c2 = *reinterpret_cast<const float2*>(Wb + 24 * 16);
        #pragma unroll
        for (int p = 0; p < 2; p++)
            h2s[p][1] = fsig_s(fmaf(h1s[p][4], c2.y, c2.x));
    }

    // Level 3 (no sigmoid, unscaled table): folded bilinear (3 FMA).
    float2 ov;
    {
        float4 c4 = *reinterpret_cast<const float4*>(Wb + 25 * 16);
        ov.x = lut2m(c4, h2s[0][0], h2s[0][1]);
        ov.y = lut2m(c4, h2s[1][0], h2s[1][1]);
    }

    const int h = h0 + ty;
    *reinterpret_cast<float2*>(&out[(((b * 32 + o) * 32 + h) * 32) + wb]) = ov;
}

extern "C" void kernel_launch(void* const* d_in, const int* in_sizes, int n_in,
                              void* d_out, int out_size) {
    const float* x  = (const float*)d_in[0];
    const float* w0 = (const float*)d_in[1];
    const float* w1 = (const float*)d_in[2];
    const float* w2 = (const float*)d_in[3];
    const float* w3 = (const float*)d_in[4];
    const int*   ci = (const int*)d_in[5];

    // 1) build all transformed tables once
    prep_kernel<<<32, 32>>>(w0, w1, w2, w3);
    // 2) D2D copy into constant bank (graph-capturable memcpy node)
    void* gsrc = nullptr;
    cudaGetSymbolAddress(&gsrc, g_wc);
    cudaMemcpyToSymbolAsync(cWc, gsrc, NTBL * sizeof(float), 0,
                            cudaMemcpyDeviceToDevice, 0);
    // 3) main eval
    dim3 grid(32, 8, 4);   // (O, B, H-quarter) — 1024 blocks, single wave
    lut_tree_kernel<<<grid, 128>>>(x, ci, (float*)d_out);
}

// round 17
// speedup vs baseline: 1.3433x; 1.3433x over previous
#include <cuda_runtime.h>

// LUT-tree conv: B=8, C=64, H=W=32, O=32, Q=8, K=3.
// R16: two kernels with Programmatic Dependent Launch overlap.
//   sig_pad_kernel: sigmoid(x) into padded planes [b][c][34][36], 0.5 halo baked.
//   lut_tree_kernel (PSS attr): stages Möbius+folded+(-log2e)-scaled tables
//   BEFORE cudaGridDependencySynchronize() (overlaps prepass), then fill =
//   pure float4 copy (no guards, no S-init), then the R9 eval core.

#define STRIDE 36
#define HROWS  10                    // 8 output rows + 2 halo
#define PLANE  (HROWS * STRIDE)      // 360 floats per channel plane in SMEM
#define GPLANE (34 * 36)             // 1224 floats per padded global plane

__device__ float g_sig[8 * 64 * GPLANE];   // padded sigmoided input

// raw sigmoid (prepass): 2 MUFU + mul/add
__device__ __forceinline__ float fsig(float x) {
    float e, r;
    asm("ex2.approx.f32 %0, %1;" : "=f"(e) : "f"(x * -1.4426950408889634f));
    asm("rcp.approx.f32 %0, %1;" : "=f"(r) : "f"(1.0f + e));
    return r;
}
// eval sigmoid: tables pre-scaled by -log2(e), so argument arrives ready
__device__ __forceinline__ float fsig_s(float y) {
    float e, r;
    asm("ex2.approx.f32 %0, %1;" : "=f"(e) : "f"(y));
    asm("rcp.approx.f32 %0, %1;" : "=f"(r) : "f"(1.0f + e));
    return r;
}

// Horner eval of multilinear interp with Möbius coeffs: 15 FMA, zero FADD.
__device__ __forceinline__ float lut4m(const float c[16],
                                       float x0, float x1, float x2, float x3) {
    float u0 = fmaf(x0, c[1],  c[0]);
    float u1 = fmaf(x0, c[3],  c[2]);
    float u2 = fmaf(x0, c[5],  c[4]);
    float u3 = fmaf(x0, c[7],  c[6]);
    float u4 = fmaf(x0, c[9],  c[8]);
    float u5 = fmaf(x0, c[11], c[10]);
    float u6 = fmaf(x0, c[13], c[12]);
    float u7 = fmaf(x0, c[15], c[14]);
    float v0 = fmaf(x1, u1, u0);
    float v1 = fmaf(x1, u3, u2);
    float v2 = fmaf(x1, u5, u4);
    float v3 = fmaf(x1, u7, u6);
    float w0 = fmaf(x2, v1, v0);
    float w1 = fmaf(x2, v3, v2);
    return fmaf(x3, w1, w0);
}

// 2-input folded LUT: 3 FMA.
__device__ __forceinline__ float lut2m(float4 c, float x0, float x1) {
    return fmaf(x1, fmaf(x0, c.w, c.z), fmaf(x0, c.y, c.x));
}

// Coeff fetch: 4x LDS.128 broadcast (uniform address).
__device__ __forceinline__ void ldc16(float c[16], const float* Wc, int lut) {
    const float4* p = reinterpret_cast<const float4*>(Wc + lut * 16);
    #pragma unroll
    for (int j = 0; j < 4; j++) {
        float4 t = p[j];
        c[4*j+0] = t.x; c[4*j+1] = t.y; c[4*j+2] = t.z; c[4*j+3] = t.w;
    }
}

// ---- Prepass: sigmoid + pad into g_sig. One block per (b,c) plane. ----
__global__ __launch_bounds__(256) void sig_pad_kernel(const float* __restrict__ x) {
    const int bc = blockIdx.x;                 // 0..511
    const float* xc = x + ((size_t)bc << 10);
    float* dst = g_sig + (size_t)bc * GPLANE;
    for (int i4 = threadIdx.x; i4 < 306; i4 += 256) {   // 34 rows x 9 float4
        const int r  = i4 / 9;
        const int c4 = (i4 % 9) * 4;
        const int ir = r - 1;
        float v[4];
        #pragma unroll
        for (int k = 0; k < 4; k++) {
            const int ic = c4 + k - 1;
            v[k] = (ir >= 0 && ir < 32 && ic >= 0 && ic < 32)
                     ? fsig(xc[(ir << 5) + ic]) : 0.5f;
        }
        *reinterpret_cast<float4*>(dst + r * 36 + c4) =
            make_float4(v[0], v[1], v[2], v[3]);
    }
}

__global__ __launch_bounds__(128, 7) void lut_tree_kernel(
    const float* __restrict__ w0, const float* __restrict__ w1,
    const float* __restrict__ w2, const float* __restrict__ w3,
    const int* __restrict__ ci, float* __restrict__ out)
{
    __shared__ __align__(16) float S[8 * PLANE];   // sigmoided channels + halo
    __shared__ __align__(16) float Wc[26 * 16];    // transformed coeffs

    const int o   = blockIdx.x;          // 0..31
    const int b   = blockIdx.y;          // 0..7
    const int h0  = blockIdx.z << 3;     // 0,8,16,24
    const int tid = threadIdx.x;

    // ---- Prologue (independent of prepass): stage + transform weights ----
    if (tid < 26) {
        const float* src;
        if (tid < 18)      src = w0 + o * 288 + tid * 16;
        else if (tid < 23) src = w1 + o * 80  + (tid - 18) * 16;
        else if (tid < 25) src = w2 + o * 32  + (tid - 23) * 16;
        else               src = w3 + o * 16;
        float t16[16];
        #pragma unroll
        for (int i = 0; i < 16; i++) t16[i] = src[i];
        #pragma unroll
        for (int d = 0; d < 4; d++) {            // Möbius finite-difference
            const int s = 1 << d;
            #pragma unroll
            for (int j = 0; j < 16; j++)
                if (j & s) t16[j] -= t16[j ^ s];
        }
        // fold constant-0.5 inputs: LUT22 & LUT25 fold dims 3,2; LUT24 dims 3,2,1.
        const int nfold = (tid == 22 || tid == 25) ? 2 : (tid == 24 ? 3 : 0);
        for (int d = 3; d > 3 - nfold; d--) {
            const int s = 1 << d;
            for (int j = 0; j < s; j++) t16[j] += 0.5f * t16[j + s];
        }
        // pre-scale by -log2(e) for all sigmoid-feeding tables (all but 25)
        if (tid != 25) {
            #pragma unroll
            for (int i = 0; i < 16; i++) t16[i] *= -1.4426950408889634f;
        }
        #pragma unroll
        for (int i = 0; i < 16; i++) Wc[tid * 16 + i] = t16[i];
    }

    // ---- Wait for prepass (PDL) ----
    cudaGridDependencySynchronize();
    __syncthreads();

    // ---- Fill: pure float4 copy of 10 padded rows per channel ----
    #pragma unroll
    for (int q = 0; q < 8; q++) {
        const int ch = ci[o * 8 + q];
        const float4* src = reinterpret_cast<const float4*>(
            g_sig + (size_t)(b * 64 + ch) * GPLANE + h0 * 36);
        float4* dst = reinterpret_cast<float4*>(S + q * PLANE);
        if (tid < 90) dst[tid] = src[tid];     // 90 float4 = 10 rows x 36 floats
    }
    __syncthreads();

    // ---- Eval: thread -> output row ty (of 8), 2 consecutive cols ----
    const int ty = tid >> 4;              // 0..7
    const int wb = (tid & 15) << 1;       // 0..30 (8B aligned)

    // Rolling feature-row pair: va = row rA, vb = row rA+1 (rA = 4l/3).
    float va[4], vb[4];
    #define LOADROW(dst, R) do {                                               \
        const float* p_ = S + ((R) / 3) * PLANE + (ty + (R) % 3) * STRIDE + wb;\
        float2 f0_ = *(const float2*)p_;                                       \
        float2 f1_ = *(const float2*)(p_ + 2);                                 \
        dst[0] = f0_.x; dst[1] = f0_.y; dst[2] = f1_.x; dst[3] = f1_.y;        \
    } while (0)

    float ing[4][2];   // current level-1 group inputs
    float h1s[2][5];   // sigmoided level-1 outputs per pixel

    LOADROW(va, 0);
    LOADROW(vb, 1);

    #pragma unroll
    for (int l = 0; l < 18; l++) {
        const int k = l & 3;
        const int g = l >> 2;
        const int rA = (4 * l) / 3;
        float c[16]; ldc16(c, Wc, l);
        #pragma unroll
        for (int p = 0; p < 2; p++) {
            float xi[4];
            #pragma unroll
            for (int i = 0; i < 4; i++) {
                const int j  = 4 * l + i;     // compile-time
                const int rr = j / 3;
                const int kw = j % 3;
                xi[i] = (rr == rA) ? va[kw + p] : vb[kw + p];
            }
            ing[k][p] = fsig_s(lut4m(c, xi[0], xi[1], xi[2], xi[3]));
        }
        if (k == 3) {                        // groups 0..3 (full LUT4)
            float cg[16]; ldc16(cg, Wc, 18 + g);
            #pragma unroll
            for (int p = 0; p < 2; p++)
                h1s[p][g] = fsig_s(lut4m(cg, ing[0][p], ing[1][p], ing[2][p], ing[3][p]));
        }
        if (l == 17) {                       // group 4: folded 2-input LUT
            float4 c4 = *reinterpret_cast<const float4*>(Wc + 22 * 16);
            #pragma unroll
            for (int p = 0; p < 2; p++)
                h1s[p][4] = fsig_s(lut2m(c4, ing[0][p], ing[1][p]));
        }
        if (l < 17) {                        // advance rolling rows
            const int rN = (4 * (l + 1)) / 3;
            if (rN == rA + 1) {
                #pragma unroll
                for (int i = 0; i < 4; i++) va[i] = vb[i];
                LOADROW(vb, rN + 1);
            } else {
                LOADROW(va, rN);
                LOADROW(vb, rN + 1);
            }
        }
    }
    #undef LOADROW

    // Level 2: LUT23 full; LUT24 folded to linear (1 FMA).
    float h2s[2][2];
    {
        float c[16]; ldc16(c, Wc, 23);
        #pragma unroll
        for (int p = 0; p < 2; p++)
            h2s[p][0] = fsig_s(lut4m(c, h1s[p][0], h1s[p][1], h1s[p][2], h1s[p][3]));
    }
    {
        float2 c2 = *reinterpret_cast<const float2*>(Wc + 24 * 16);
        #pragma unroll
        for (int p = 0; p < 2; p++)
            h2s[p][1] = fsig_s(fmaf(h1s[p][4], c2.y, c2.x));
    }

    // Level 3 (no sigmoid, unscaled table): folded bilinear (3 FMA).
    float2 ov;
    {
        float4 c4 = *reinterpret_cast<const float4*>(Wc + 25 * 16);
        ov.x = lut2m(c4, h2s[0][0], h2s[0][1]);
        ov.y = lut2m(c4, h2s[1][0], h2s[1][1]);
    }

    const int h = h0 + ty;
    *reinterpret_cast<float2*>(&out[(((b * 32 + o) * 32 + h) * 32) + wb]) = ov;
}

extern "C" void kernel_launch(void* const* d_in, const int* in_sizes, int n_in,
                              void* d_out, int out_size) {
    const float* x  = (const float*)d_in[0];
    const float* w0 = (const float*)d_in[1];
    const float* w1 = (const float*)d_in[2];
    const float* w2 = (const float*)d_in[3];
    const float* w3 = (const float*)d_in[4];
    const int*   ci = (const int*)d_in[5];

    // 1) prepass: sigmoid + pad
    sig_pad_kernel<<<512, 256>>>(x);

    // 2) main eval, launched with Programmatic Stream Serialization so its
    //    weight-staging prologue overlaps the prepass tail.
    cudaLaunchConfig_t cfg = {};
    cfg.gridDim  = dim3(32, 8, 4);
    cfg.blockDim = dim3(128, 1, 1);
    cfg.stream   = 0;
    cudaLaunchAttribute attr[1];
    attr[0].id = cudaLaunchAttributeProgrammaticStreamSerialization;
    attr[0].val.programmaticStreamSerializationAllowed = 1;
    cfg.attrs = attr;
    cfg.numAttrs = 1;
    cudaLaunchKernelEx(&cfg, lut_tree_kernel, w0, w1, w2, w3, ci, (float*)d_out);
}